// round 15
// baseline (speedup 1.0000x reference)
#include <cuda_runtime.h>
#include <cstdint>

// ==================== problem constants ====================
#define BATCH 4
#define C_DIM 512
#define N_Q   512
#define HW_T  76800
#define MBLK  3072
#define NMBLK 25           // 76800 / 3072
#define CHB   16           // channels per CTA in pass1
#define NCBLK 32           // 512 / 16
#define ALPHA 0.1953125f   // 100/512 (exact in fp32)

// Deterministic partials / results (no atomics anywhere).
__device__ float4 g_part[BATCH][C_DIM][NMBLK];   // (sum_t, sum_t*x, sum_t*y, 0)
__device__ float2 g_partS[BATCH][NMBLK];         // (sum_x, sum_y)
__device__ float4 g_T[BATCH][C_DIM];             // reduced moment vectors
__device__ float2 g_S[BATCH];                    // (Sx, Sy)

// ==================== pass 1: stream trg_desc once, build moments ====================
// T1[c] = sum_m t[c,m], Tx[c] = sum_m t[c,m]*x_m, Ty[c] = sum_m t[c,m]*y_m.
// R12 structure exactly (proven 98.5us @ 81% DRAM): MBLK=3072, coalesced
// LDG.128 + __ldcs, coords in 6 float4 registers, per-channel butterfly.
// R13 (smem tree) and R14 (MBLK=5120) both regressed through OCCUPANCY:
// DRAM% tracks warps-in-flight here. This round's single change:
// __launch_bounds__(256, 6) to cap regs ~42 -> 6 CTAs/SM (was 5).
__global__ __launch_bounds__(256, 6)
void pass1(const float* __restrict__ trg_desc, const float* __restrict__ trg_xy)
{
    __shared__ float4 red[CHB][8];         // per-channel, per-warp partials
    __shared__ float2 redS[8];

    const int mb  = blockIdx.x;
    const int cb  = blockIdx.y;
    const int b   = blockIdx.z;
    const int tid = threadIdx.x;
    const int w   = tid >> 5;
    const int lane = tid & 31;

    // coordinates for this thread's fixed m-positions (registers, not smem)
    const float4* X4 = (const float4*)(trg_xy + (size_t)b * 2 * HW_T + mb * MBLK);
    const float4* Y4 = (const float4*)(trg_xy + (size_t)b * 2 * HW_T + HW_T + mb * MBLK);
    float4 xr[3], yr[3];
    #pragma unroll
    for (int i = 0; i < 3; ++i) {
        xr[i] = X4[tid + i * 256];
        yr[i] = Y4[tid + i * 256];
    }

    // per-channel streaming reduction
    #pragma unroll 2
    for (int ch = 0; ch < CHB; ++ch) {
        const int c = cb * CHB + ch;
        const float4* T4 = (const float4*)(trg_desc
                          + ((size_t)b * C_DIM + c) * HW_T + mb * MBLK);
        float s1 = 0.f, sx = 0.f, sy = 0.f;
        #pragma unroll
        for (int i = 0; i < 3; ++i) {
            float4 v  = __ldcs(T4 + tid + i * 256);   // read-once: evict-first
            float4 xv = xr[i];
            float4 yv = yr[i];
            s1 += (v.x + v.y) + (v.z + v.w);
            sx = fmaf(v.x, xv.x, fmaf(v.y, xv.y, fmaf(v.z, xv.z, fmaf(v.w, xv.w, sx))));
            sy = fmaf(v.x, yv.x, fmaf(v.y, yv.y, fmaf(v.z, yv.z, fmaf(v.w, yv.w, sy))));
        }
        #pragma unroll
        for (int o = 16; o; o >>= 1) {
            s1 += __shfl_xor_sync(0xffffffffu, s1, o);
            sx += __shfl_xor_sync(0xffffffffu, sx, o);
            sy += __shfl_xor_sync(0xffffffffu, sy, o);
        }
        if (lane == 0) red[ch][w] = make_float4(s1, sx, sy, 0.f);
    }

    // coordinate sums (only one cblk needs them; from the same registers)
    if (cb == 0) {
        float ax = 0.f, ay = 0.f;
        #pragma unroll
        for (int i = 0; i < 3; ++i) {
            ax += (xr[i].x + xr[i].y) + (xr[i].z + xr[i].w);
            ay += (yr[i].x + yr[i].y) + (yr[i].z + yr[i].w);
        }
        #pragma unroll
        for (int o = 16; o; o >>= 1) {
            ax += __shfl_xor_sync(0xffffffffu, ax, o);
            ay += __shfl_xor_sync(0xffffffffu, ay, o);
        }
        if (lane == 0) redS[w] = make_float2(ax, ay);
    }
    __syncthreads();

    if (tid < CHB) {
        float4 a = make_float4(0.f, 0.f, 0.f, 0.f);
        #pragma unroll
        for (int j = 0; j < 8; ++j) {
            float4 p = red[tid][j];
            a.x += p.x; a.y += p.y; a.z += p.z;
        }
        g_part[b][cb * CHB + tid][mb] = a;
    }
    if (cb == 0 && tid == 0) {
        float2 s = make_float2(0.f, 0.f);
        #pragma unroll
        for (int j = 0; j < 8; ++j) { s.x += redS[j].x; s.y += redS[j].y; }
        g_partS[b][mb] = s;
    }
}

// ==================== pass 2: reduce m-block partials (done ONCE) ====================
__global__ void pass2()
{
    const int b = blockIdx.x;
    const int c = threadIdx.x;     // 512 threads
    float4 acc = make_float4(0.f, 0.f, 0.f, 0.f);
    #pragma unroll
    for (int k = 0; k < NMBLK; ++k) {
        float4 p = g_part[b][c][k];
        acc.x += p.x; acc.y += p.y; acc.z += p.z;
    }
    g_T[b][c] = acc;
    if (c == 0) {
        float2 s = make_float2(0.f, 0.f);
        #pragma unroll
        for (int k = 0; k < NMBLK; ++k) {
            s.x += g_partS[b][k].x; s.y += g_partS[b][k].y;
        }
        g_S[b] = s;
    }
}

// ==================== pass 3: per-keypoint dots + final ratio ====================
// out_x(n) = (Sx + a*d_n.Tx) / (HW + a*d_n.T1), a = 100/512.
// Latency-optimized: 256 CTAs (8 kp x 32 ch-groups), 16 fully-unrolled
// independent loads per thread (MLP=16 -> ~1 amortized DRAM roundtrip).
__global__ __launch_bounds__(256)
void pass3(const float* __restrict__ src_desc, float* __restrict__ out)
{
    __shared__ float4 Tsm[C_DIM];            // 8KB (L2 broadcast)
    __shared__ float red3[3][8][8];          // [val][warp][kp]

    const int b  = blockIdx.y;
    const int nb = blockIdx.x * 8;
    const int tid = threadIdx.x;
    const int lane = tid & 31;
    const int w  = tid >> 5;
    const int nl = tid & 7;                  // keypoint within CTA (0..7)
    const int cg = tid >> 3;                 // channel group (0..31), 16 ch each

    #pragma unroll
    for (int c = tid; c < C_DIM; c += 256) Tsm[c] = g_T[b][c];
    __syncthreads();

    const float* A = src_desc + (size_t)b * C_DIM * N_Q + nb + nl;
    float av[16];
    #pragma unroll
    for (int j = 0; j < 16; ++j)             // 16 independent loads in flight
        av[j] = A[(size_t)(cg * 16 + j) * N_Q];

    float a1 = 0.f, ax = 0.f, ay = 0.f;
    #pragma unroll
    for (int j = 0; j < 16; ++j) {
        float4 t = Tsm[cg * 16 + j];
        a1 = fmaf(av[j], t.x, a1);
        ax = fmaf(av[j], t.y, ax);
        ay = fmaf(av[j], t.z, ay);
    }

    // intra-warp: lanes nl, nl+8, nl+16, nl+24 hold the 4 cg-slices of kp nl
    #pragma unroll
    for (int o = 8; o <= 16; o <<= 1) {
        a1 += __shfl_xor_sync(0xffffffffu, a1, o);
        ax += __shfl_xor_sync(0xffffffffu, ax, o);
        ay += __shfl_xor_sync(0xffffffffu, ay, o);
    }
    if (lane < 8) {
        red3[0][w][lane] = a1;
        red3[1][w][lane] = ax;
        red3[2][w][lane] = ay;
    }
    __syncthreads();

    if (tid < 8) {
        float s1 = 0.f, sx = 0.f, sy = 0.f;
        #pragma unroll
        for (int g = 0; g < 8; ++g) {
            s1 += red3[0][g][tid];
            sx += red3[1][g][tid];
            sy += red3[2][g][tid];
        }
        float2 S = g_S[b];
        float D = fmaf(ALPHA, s1, (float)HW_T);
        float inv = 1.0f / D;
        const int n = nb + tid;
        out[(size_t)b * 2 * N_Q + n]       = fmaf(ALPHA, sx, S.x) * inv;
        out[(size_t)b * 2 * N_Q + N_Q + n] = fmaf(ALPHA, sy, S.y) * inv;
    }
}

// ==================== launch ====================
extern "C" void kernel_launch(void* const* d_in, const int* in_sizes, int n_in,
                              void* d_out, int out_size)
{
    // metadata order: kpt_2D_src, kpt_2D_trg, kpt_desc_norm_src, kpt_desc_norm_trg
    const float* kpt_trg = (const float*)d_in[1];
    const float* dsrc    = (const float*)d_in[2];
    const float* dtrg    = (const float*)d_in[3];
    float* out = (float*)d_out;

    pass1<<<dim3(NMBLK, NCBLK, BATCH), 256>>>(dtrg, kpt_trg);
    pass2<<<BATCH, C_DIM>>>();
    pass3<<<dim3(N_Q / 8, BATCH), 256>>>(dsrc, out);
}

// round 16
// speedup vs baseline: 1.2320x; 1.2320x over previous
#include <cuda_runtime.h>
#include <cstdint>

// ==================== problem constants ====================
#define BATCH 4
#define C_DIM 512
#define N_Q   512
#define HW_T  76800
#define MBLK  3072
#define NMBLK 25           // 76800 / 3072
#define CHB   8            // channels per CTA in pass1 (R16: halved for wave granularity)
#define NCBLK 64           // 512 / 8
#define ALPHA 0.1953125f   // 100/512 (exact in fp32)

// Deterministic partials / results (no atomics anywhere).
__device__ float4 g_part[BATCH][C_DIM][NMBLK];   // (sum_t, sum_t*x, sum_t*y, 0)
__device__ float2 g_partS[BATCH][NMBLK];         // (sum_x, sum_y)
__device__ float4 g_T[BATCH][C_DIM];             // reduced moment vectors
__device__ float2 g_S[BATCH];                    // (Sx, Sy)

// ==================== pass 1: stream trg_desc once, build moments ====================
// T1[c] = sum_m t[c,m], Tx[c] = sum_m t[c,m]*x_m, Ty[c] = sum_m t[c,m]*y_m.
// R12 hot loop EXACTLY (proven 98.5us @ 81.4% DRAM, regs=48, 5 CTA/SM):
// coalesced LDG.128 + __ldcs, coords in 6 float4 registers, per-channel
// butterfly. R13 (smem tree), R14 (bigger MBLK), R15 (forced 6 CTA/SM) all
// regressed -> loop body frozen. R16's single change: CHB 16->8 (grid
// 3200->6400 CTAs) to halve the partial-wave tail (4.3 -> 8.6 waves).
__global__ __launch_bounds__(256)
void pass1(const float* __restrict__ trg_desc, const float* __restrict__ trg_xy)
{
    __shared__ float4 red[CHB][8];         // per-channel, per-warp partials
    __shared__ float2 redS[8];

    const int mb  = blockIdx.x;
    const int cb  = blockIdx.y;
    const int b   = blockIdx.z;
    const int tid = threadIdx.x;
    const int w   = tid >> 5;
    const int lane = tid & 31;

    // coordinates for this thread's fixed m-positions (registers, not smem)
    const float4* X4 = (const float4*)(trg_xy + (size_t)b * 2 * HW_T + mb * MBLK);
    const float4* Y4 = (const float4*)(trg_xy + (size_t)b * 2 * HW_T + HW_T + mb * MBLK);
    float4 xr[3], yr[3];
    #pragma unroll
    for (int i = 0; i < 3; ++i) {
        xr[i] = X4[tid + i * 256];
        yr[i] = Y4[tid + i * 256];
    }

    // per-channel streaming reduction
    #pragma unroll 2
    for (int ch = 0; ch < CHB; ++ch) {
        const int c = cb * CHB + ch;
        const float4* T4 = (const float4*)(trg_desc
                          + ((size_t)b * C_DIM + c) * HW_T + mb * MBLK);
        float s1 = 0.f, sx = 0.f, sy = 0.f;
        #pragma unroll
        for (int i = 0; i < 3; ++i) {
            float4 v  = __ldcs(T4 + tid + i * 256);   // read-once: evict-first
            float4 xv = xr[i];
            float4 yv = yr[i];
            s1 += (v.x + v.y) + (v.z + v.w);
            sx = fmaf(v.x, xv.x, fmaf(v.y, xv.y, fmaf(v.z, xv.z, fmaf(v.w, xv.w, sx))));
            sy = fmaf(v.x, yv.x, fmaf(v.y, yv.y, fmaf(v.z, yv.z, fmaf(v.w, yv.w, sy))));
        }
        #pragma unroll
        for (int o = 16; o; o >>= 1) {
            s1 += __shfl_xor_sync(0xffffffffu, s1, o);
            sx += __shfl_xor_sync(0xffffffffu, sx, o);
            sy += __shfl_xor_sync(0xffffffffu, sy, o);
        }
        if (lane == 0) red[ch][w] = make_float4(s1, sx, sy, 0.f);
    }

    // coordinate sums (only one cblk needs them; from the same registers)
    if (cb == 0) {
        float ax = 0.f, ay = 0.f;
        #pragma unroll
        for (int i = 0; i < 3; ++i) {
            ax += (xr[i].x + xr[i].y) + (xr[i].z + xr[i].w);
            ay += (yr[i].x + yr[i].y) + (yr[i].z + yr[i].w);
        }
        #pragma unroll
        for (int o = 16; o; o >>= 1) {
            ax += __shfl_xor_sync(0xffffffffu, ax, o);
            ay += __shfl_xor_sync(0xffffffffu, ay, o);
        }
        if (lane == 0) redS[w] = make_float2(ax, ay);
    }
    __syncthreads();

    if (tid < CHB) {
        float4 a = make_float4(0.f, 0.f, 0.f, 0.f);
        #pragma unroll
        for (int j = 0; j < 8; ++j) {
            float4 p = red[tid][j];
            a.x += p.x; a.y += p.y; a.z += p.z;
        }
        g_part[b][cb * CHB + tid][mb] = a;
    }
    if (cb == 0 && tid == 0) {
        float2 s = make_float2(0.f, 0.f);
        #pragma unroll
        for (int j = 0; j < 8; ++j) { s.x += redS[j].x; s.y += redS[j].y; }
        g_partS[b][mb] = s;
    }
}

// ==================== pass 2: reduce m-block partials (done ONCE) ====================
__global__ void pass2()
{
    const int b = blockIdx.x;
    const int c = threadIdx.x;     // 512 threads
    float4 acc = make_float4(0.f, 0.f, 0.f, 0.f);
    #pragma unroll
    for (int k = 0; k < NMBLK; ++k) {
        float4 p = g_part[b][c][k];
        acc.x += p.x; acc.y += p.y; acc.z += p.z;
    }
    g_T[b][c] = acc;
    if (c == 0) {
        float2 s = make_float2(0.f, 0.f);
        #pragma unroll
        for (int k = 0; k < NMBLK; ++k) {
            s.x += g_partS[b][k].x; s.y += g_partS[b][k].y;
        }
        g_S[b] = s;
    }
}

// ==================== pass 3: per-keypoint dots + final ratio ====================
// out_x(n) = (Sx + a*d_n.Tx) / (HW + a*d_n.T1), a = 100/512.
// Latency-optimized: 256 CTAs (8 kp x 32 ch-groups), 16 fully-unrolled
// independent loads per thread (MLP=16 -> ~1 amortized DRAM roundtrip).
__global__ __launch_bounds__(256)
void pass3(const float* __restrict__ src_desc, float* __restrict__ out)
{
    __shared__ float4 Tsm[C_DIM];            // 8KB (L2 broadcast)
    __shared__ float red3[3][8][8];          // [val][warp][kp]

    const int b  = blockIdx.y;
    const int nb = blockIdx.x * 8;
    const int tid = threadIdx.x;
    const int lane = tid & 31;
    const int w  = tid >> 5;
    const int nl = tid & 7;                  // keypoint within CTA (0..7)
    const int cg = tid >> 3;                 // channel group (0..31), 16 ch each

    #pragma unroll
    for (int c = tid; c < C_DIM; c += 256) Tsm[c] = g_T[b][c];
    __syncthreads();

    const float* A = src_desc + (size_t)b * C_DIM * N_Q + nb + nl;
    float av[16];
    #pragma unroll
    for (int j = 0; j < 16; ++j)             // 16 independent loads in flight
        av[j] = A[(size_t)(cg * 16 + j) * N_Q];

    float a1 = 0.f, ax = 0.f, ay = 0.f;
    #pragma unroll
    for (int j = 0; j < 16; ++j) {
        float4 t = Tsm[cg * 16 + j];
        a1 = fmaf(av[j], t.x, a1);
        ax = fmaf(av[j], t.y, ax);
        ay = fmaf(av[j], t.z, ay);
    }

    // intra-warp: lanes nl, nl+8, nl+16, nl+24 hold the 4 cg-slices of kp nl
    #pragma unroll
    for (int o = 8; o <= 16; o <<= 1) {
        a1 += __shfl_xor_sync(0xffffffffu, a1, o);
        ax += __shfl_xor_sync(0xffffffffu, ax, o);
        ay += __shfl_xor_sync(0xffffffffu, ay, o);
    }
    if (lane < 8) {
        red3[0][w][lane] = a1;
        red3[1][w][lane] = ax;
        red3[2][w][lane] = ay;
    }
    __syncthreads();

    if (tid < 8) {
        float s1 = 0.f, sx = 0.f, sy = 0.f;
        #pragma unroll
        for (int g = 0; g < 8; ++g) {
            s1 += red3[0][g][tid];
            sx += red3[1][g][tid];
            sy += red3[2][g][tid];
        }
        float2 S = g_S[b];
        float D = fmaf(ALPHA, s1, (float)HW_T);
        float inv = 1.0f / D;
        const int n = nb + tid;
        out[(size_t)b * 2 * N_Q + n]       = fmaf(ALPHA, sx, S.x) * inv;
        out[(size_t)b * 2 * N_Q + N_Q + n] = fmaf(ALPHA, sy, S.y) * inv;
    }
}

// ==================== launch ====================
extern "C" void kernel_launch(void* const* d_in, const int* in_sizes, int n_in,
                              void* d_out, int out_size)
{
    // metadata order: kpt_2D_src, kpt_2D_trg, kpt_desc_norm_src, kpt_desc_norm_trg
    const float* kpt_trg = (const float*)d_in[1];
    const float* dsrc    = (const float*)d_in[2];
    const float* dtrg    = (const float*)d_in[3];
    float* out = (float*)d_out;

    pass1<<<dim3(NMBLK, NCBLK, BATCH), 256>>>(dtrg, kpt_trg);
    pass2<<<BATCH, C_DIM>>>();
    pass3<<<dim3(N_Q / 8, BATCH), 256>>>(dsrc, out);
}

// round 17
// speedup vs baseline: 1.2755x; 1.0353x over previous
#include <cuda_runtime.h>
#include <cstdint>

// ==================== problem constants ====================
#define BATCH 4
#define C_DIM 512
#define N_Q   512
#define HW_T  76800
#define MBLK  3072
#define NMBLK 25           // 76800 / 3072
#define CHB   4            // channels per CTA in pass1 (R17: halved again for wave granularity)
#define NCBLK 128          // 512 / 4
#define ALPHA 0.1953125f   // 100/512 (exact in fp32)

// Deterministic partials / results (no atomics anywhere).
__device__ float4 g_part[BATCH][C_DIM][NMBLK];   // (sum_t, sum_t*x, sum_t*y, 0)
__device__ float2 g_partS[BATCH][NMBLK];         // (sum_x, sum_y)
__device__ float4 g_T[BATCH][C_DIM];             // reduced moment vectors
__device__ float2 g_S[BATCH];                    // (Sx, Sy)

// ==================== pass 1: stream trg_desc once, build moments ====================
// T1[c] = sum_m t[c,m], Tx[c] = sum_m t[c,m]*x_m, Ty[c] = sum_m t[c,m]*y_m.
// Hot loop FROZEN at the R12/R16 configuration (95.8us @ 83.7% DRAM, regs=48):
// coalesced LDG.128 + __ldcs, coords in 6 float4 registers, per-channel
// butterfly. R17's single pass1 change: CHB 8->4 (grid 6400->12800 CTAs,
// 8.65 -> 17.3 waves) to shrink the partial-wave tail further. Coord L2
// traffic rises to 50% of desc bytes -- still under the LTS cap.
__global__ __launch_bounds__(256)
void pass1(const float* __restrict__ trg_desc, const float* __restrict__ trg_xy)
{
    __shared__ float4 red[CHB][8];         // per-channel, per-warp partials
    __shared__ float2 redS[8];

    const int mb  = blockIdx.x;
    const int cb  = blockIdx.y;
    const int b   = blockIdx.z;
    const int tid = threadIdx.x;
    const int w   = tid >> 5;
    const int lane = tid & 31;

    // coordinates for this thread's fixed m-positions (registers, not smem)
    const float4* X4 = (const float4*)(trg_xy + (size_t)b * 2 * HW_T + mb * MBLK);
    const float4* Y4 = (const float4*)(trg_xy + (size_t)b * 2 * HW_T + HW_T + mb * MBLK);
    float4 xr[3], yr[3];
    #pragma unroll
    for (int i = 0; i < 3; ++i) {
        xr[i] = X4[tid + i * 256];
        yr[i] = Y4[tid + i * 256];
    }

    // per-channel streaming reduction
    #pragma unroll 2
    for (int ch = 0; ch < CHB; ++ch) {
        const int c = cb * CHB + ch;
        const float4* T4 = (const float4*)(trg_desc
                          + ((size_t)b * C_DIM + c) * HW_T + mb * MBLK);
        float s1 = 0.f, sx = 0.f, sy = 0.f;
        #pragma unroll
        for (int i = 0; i < 3; ++i) {
            float4 v  = __ldcs(T4 + tid + i * 256);   // read-once: evict-first
            float4 xv = xr[i];
            float4 yv = yr[i];
            s1 += (v.x + v.y) + (v.z + v.w);
            sx = fmaf(v.x, xv.x, fmaf(v.y, xv.y, fmaf(v.z, xv.z, fmaf(v.w, xv.w, sx))));
            sy = fmaf(v.x, yv.x, fmaf(v.y, yv.y, fmaf(v.z, yv.z, fmaf(v.w, yv.w, sy))));
        }
        #pragma unroll
        for (int o = 16; o; o >>= 1) {
            s1 += __shfl_xor_sync(0xffffffffu, s1, o);
            sx += __shfl_xor_sync(0xffffffffu, sx, o);
            sy += __shfl_xor_sync(0xffffffffu, sy, o);
        }
        if (lane == 0) red[ch][w] = make_float4(s1, sx, sy, 0.f);
    }

    // coordinate sums (only one cblk needs them; from the same registers)
    if (cb == 0) {
        float ax = 0.f, ay = 0.f;
        #pragma unroll
        for (int i = 0; i < 3; ++i) {
            ax += (xr[i].x + xr[i].y) + (xr[i].z + xr[i].w);
            ay += (yr[i].x + yr[i].y) + (yr[i].z + yr[i].w);
        }
        #pragma unroll
        for (int o = 16; o; o >>= 1) {
            ax += __shfl_xor_sync(0xffffffffu, ax, o);
            ay += __shfl_xor_sync(0xffffffffu, ay, o);
        }
        if (lane == 0) redS[w] = make_float2(ax, ay);
    }
    __syncthreads();

    if (tid < CHB) {
        float4 a = make_float4(0.f, 0.f, 0.f, 0.f);
        #pragma unroll
        for (int j = 0; j < 8; ++j) {
            float4 p = red[tid][j];
            a.x += p.x; a.y += p.y; a.z += p.z;
        }
        g_part[b][cb * CHB + tid][mb] = a;
    }
    if (cb == 0 && tid == 0) {
        float2 s = make_float2(0.f, 0.f);
        #pragma unroll
        for (int j = 0; j < 8; ++j) { s.x += redS[j].x; s.y += redS[j].y; }
        g_partS[b][mb] = s;
    }
}

// ==================== pass 2: reduce m-block partials (wide: 1 task/thread) ====================
// 2048 (b,c) tasks over 8 CTAs x 256 threads; 25-load chain fully unrolled.
__global__ __launch_bounds__(256)
void pass2()
{
    const int task = blockIdx.x * 256 + threadIdx.x;   // 0..2047
    const int b = task >> 9;
    const int c = task & 511;
    float4 acc = make_float4(0.f, 0.f, 0.f, 0.f);
    #pragma unroll
    for (int k = 0; k < NMBLK; ++k) {
        float4 p = g_part[b][c][k];
        acc.x += p.x; acc.y += p.y; acc.z += p.z;
    }
    g_T[b][c] = acc;
    if (c == 0) {
        float2 s = make_float2(0.f, 0.f);
        #pragma unroll
        for (int k = 0; k < NMBLK; ++k) {
            s.x += g_partS[b][k].x; s.y += g_partS[b][k].y;
        }
        g_S[b] = s;
    }
}

// ==================== pass 3: per-keypoint dots + final ratio ====================
// out_x(n) = (Sx + a*d_n.Tx) / (HW + a*d_n.T1), a = 100/512.
// Latency-optimized: 256 CTAs (8 kp x 32 ch-groups), 16 fully-unrolled
// independent loads per thread (MLP=16 -> ~1 amortized DRAM roundtrip).
__global__ __launch_bounds__(256)
void pass3(const float* __restrict__ src_desc, float* __restrict__ out)
{
    __shared__ float4 Tsm[C_DIM];            // 8KB (L2 broadcast)
    __shared__ float red3[3][8][8];          // [val][warp][kp]

    const int b  = blockIdx.y;
    const int nb = blockIdx.x * 8;
    const int tid = threadIdx.x;
    const int lane = tid & 31;
    const int w  = tid >> 5;
    const int nl = tid & 7;                  // keypoint within CTA (0..7)
    const int cg = tid >> 3;                 // channel group (0..31), 16 ch each

    #pragma unroll
    for (int c = tid; c < C_DIM; c += 256) Tsm[c] = g_T[b][c];
    __syncthreads();

    const float* A = src_desc + (size_t)b * C_DIM * N_Q + nb + nl;
    float av[16];
    #pragma unroll
    for (int j = 0; j < 16; ++j)             // 16 independent loads in flight
        av[j] = A[(size_t)(cg * 16 + j) * N_Q];

    float a1 = 0.f, ax = 0.f, ay = 0.f;
    #pragma unroll
    for (int j = 0; j < 16; ++j) {
        float4 t = Tsm[cg * 16 + j];
        a1 = fmaf(av[j], t.x, a1);
        ax = fmaf(av[j], t.y, ax);
        ay = fmaf(av[j], t.z, ay);
    }

    // intra-warp: lanes nl, nl+8, nl+16, nl+24 hold the 4 cg-slices of kp nl
    #pragma unroll
    for (int o = 8; o <= 16; o <<= 1) {
        a1 += __shfl_xor_sync(0xffffffffu, a1, o);
        ax += __shfl_xor_sync(0xffffffffu, ax, o);
        ay += __shfl_xor_sync(0xffffffffu, ay, o);
    }
    if (lane < 8) {
        red3[0][w][lane] = a1;
        red3[1][w][lane] = ax;
        red3[2][w][lane] = ay;
    }
    __syncthreads();

    if (tid < 8) {
        float s1 = 0.f, sx = 0.f, sy = 0.f;
        #pragma unroll
        for (int g = 0; g < 8; ++g) {
            s1 += red3[0][g][tid];
            sx += red3[1][g][tid];
            sy += red3[2][g][tid];
        }
        float2 S = g_S[b];
        float D = fmaf(ALPHA, s1, (float)HW_T);
        float inv = 1.0f / D;
        const int n = nb + tid;
        out[(size_t)b * 2 * N_Q + n]       = fmaf(ALPHA, sx, S.x) * inv;
        out[(size_t)b * 2 * N_Q + N_Q + n] = fmaf(ALPHA, sy, S.y) * inv;
    }
}

// ==================== launch ====================
extern "C" void kernel_launch(void* const* d_in, const int* in_sizes, int n_in,
                              void* d_out, int out_size)
{
    // metadata order: kpt_2D_src, kpt_2D_trg, kpt_desc_norm_src, kpt_desc_norm_trg
    const float* kpt_trg = (const float*)d_in[1];
    const float* dsrc    = (const float*)d_in[2];
    const float* dtrg    = (const float*)d_in[3];
    float* out = (float*)d_out;

    pass1<<<dim3(NMBLK, NCBLK, BATCH), 256>>>(dtrg, kpt_trg);
    pass2<<<8, 256>>>();
    pass3<<<dim3(N_Q / 8, BATCH), 256>>>(dsrc, out);
}